// round 6
// baseline (speedup 1.0000x reference)
#include <cuda_runtime.h>
#include <cstdint>

#define NB 16
#define NTH 448
#define G0T 224          // threads 0..223: layer0 group (200 active)
                         // threads 224..447: layer1 group (200 active)
#define HH 50
#define GG 200
#define TSTEPS 512
#define IIN 12
#define BTOT 2048

#define K0 64            // layer0 concat input: [x(12)|h0(50)|pad2]
#define K1 112           // layer1 concat input: [h0(50)|pad6|h1(50)|pad6]
#define RSTR 208         // partial-row stride (200 rows padded)

// smem float offsets
#define IN0_OFF 0                        // [NB][K0]
#define IN1_OFF (IN0_OFF + NB*K0)        // [2][NB][K1] double buffered
#define B0_OFF  (IN1_OFF + 2*NB*K1)      // [GG]
#define B1_OFF  (B0_OFF + GG)            // [GG]
#define G0_OFF  (B1_OFF + GG)            // [64][RSTR]  (ks*16+b, row)
#define G1_OFF  (G0_OFF + 64*RSTR)       // [64][RSTR]
#define SMEM_FLOATS (G1_OFF + 64*RSTR)
#define SMEM_BYTES (SMEM_FLOATS*4)

#define BARRIER(id,n) asm volatile("bar.sync %0, %1;" :: "r"(id), "r"(n) : "memory")

typedef unsigned long long ull;

__device__ __forceinline__ ull fma2(ull a, ull b, ull c) {
    ull d;
    asm("fma.rn.f32x2 %0, %1, %2, %3;" : "=l"(d) : "l"(a), "l"(b), "l"(c));
    return d;
}
__device__ __forceinline__ float sumh(ull v) {
    float lo = __uint_as_float((unsigned)(v & 0xffffffffull));
    float hi = __uint_as_float((unsigned)(v >> 32));
    return lo + hi;
}
__device__ __forceinline__ ull pk(float a, float b) {
    return (ull)__float_as_uint(a) | ((ull)__float_as_uint(b) << 32);
}
__device__ __forceinline__ float fsigmoid(float x) {
    float e = __expf(-x);
    return __fdividef(1.0f, 1.0f + e);
}
__device__ __forceinline__ float ftanh(float x) {
    float a = fabsf(x);
    float e = __expf(2.0f * a);
    float r = 1.0f - __fdividef(2.0f, e + 1.0f);
    return copysignf(r, x);
}
// layer0 concat k: [x(12)|h0(50)|pad2]
__device__ __forceinline__ float wl0(const float* wi, const float* wh, int r, int f) {
    if (f < IIN) return wi[r * IIN + f];
    if (f < IIN + HH) return wh[r * HH + (f - IIN)];
    return 0.f;
}
// layer1 concat k: [h0(50)|pad6|h1(50)|pad6]
__device__ __forceinline__ float wl1(const float* wi, const float* wh, int r, int f) {
    if (f < HH) return wi[r * HH + f];
    if (f >= 56 && f < 56 + HH) return wh[r * HH + (f - 56)];
    return 0.f;
}

__global__ void __launch_bounds__(NTH, 1)
lstm_kernel(const float* __restrict__ x,
            const float* __restrict__ w_ih0, const float* __restrict__ w_hh0,
            const float* __restrict__ b_ih0, const float* __restrict__ b_hh0,
            const float* __restrict__ w_ih1, const float* __restrict__ w_hh1,
            const float* __restrict__ b_ih1, const float* __restrict__ b_hh1,
            const float* __restrict__ w_out, const float* __restrict__ b_out,
            float* __restrict__ out) {
    extern __shared__ float smem[];
    float* in0   = smem + IN0_OFF;   // [NB][K0]
    float* in1   = smem + IN1_OFF;   // [2][NB][K1]
    float* bias0 = smem + B0_OFF;
    float* bias1 = smem + B1_OFF;
    float* g0    = smem + G0_OFF;    // [ks*16+b][RSTR rows]
    float* g1    = smem + G1_OFF;

    const int tid = threadIdx.x;
    const int bbase = blockIdx.x * NB;

    for (int i = tid; i < NB * K0; i += NTH)     in0[i] = 0.f;
    for (int i = tid; i < 2 * NB * K1; i += NTH) in1[i] = 0.f;
    for (int i = tid; i < GG; i += NTH) {
        bias0[i] = b_ih0[i] + b_hh0[i];
        bias1[i] = b_ih1[i] + b_hh1[i];
    }
    __syncthreads();
    if (tid < 96) {   // stage x(0)
        int b = tid / 6, p = tid % 6;
        *reinterpret_cast<float2*>(&in0[b * K0 + 2 * p]) =
            *reinterpret_cast<const float2*>(&x[((size_t)(bbase + b) * TSTEPS) * IIN + 2 * p]);
    }
    __syncthreads();

    if (tid < G0T) {
        // ================= LAYER-0 GROUP =================
        const bool act = tid < 200;
        const int q = tid % 50, ks = tid / 50;     // rows 4q..4q+3, k slice [16ks,16ks+16)
        ull w0[4][8];
        if (act) {
#pragma unroll
            for (int r = 0; r < 4; r++)
#pragma unroll
                for (int i = 0; i < 8; i++) {
                    int f = ks * 16 + 2 * i;
                    w0[r][i] = pk(wl0(w_ih0, w_hh0, 4 * q + r, f),
                                  wl0(w_ih0, w_hh0, 4 * q + r, f + 1));
                }
        }
        const float* ib = in0 + ks * 16;
        float* gw = g0 + (size_t)(ks * 16) * RSTR + 4 * q;
        float c0s[4] = {0.f, 0.f, 0.f, 0.f};
        const int xb = tid / 6, xp = tid % 6;

        for (int s = 0; s <= TSTEPS; s++) {
            float2 xpre;
            if (s < TSTEPS) {
                if (tid < 96) {
                    int tn = (s + 1 < TSTEPS) ? s + 1 : TSTEPS - 1;
                    xpre = *reinterpret_cast<const float2*>(
                        &x[((size_t)(bbase + xb) * TSTEPS + tn) * IIN + 2 * xp]);
                }
                if (act) {
#pragma unroll
                    for (int wv = 0; wv < 4; wv++) {
                        ull a[4][4];
#pragma unroll
                        for (int r = 0; r < 4; r++)
#pragma unroll
                            for (int b = 0; b < 4; b++) a[r][b] = 0ull;
#pragma unroll
                        for (int i = 0; i < 4; i++) {
#pragma unroll
                            for (int b = 0; b < 4; b++) {
                                ulonglong2 v = *reinterpret_cast<const ulonglong2*>(
                                    &ib[(wv * 4 + b) * K0 + i * 4]);
                                a[0][b] = fma2(w0[0][2*i], v.x, a[0][b]);
                                a[0][b] = fma2(w0[0][2*i+1], v.y, a[0][b]);
                                a[1][b] = fma2(w0[1][2*i], v.x, a[1][b]);
                                a[1][b] = fma2(w0[1][2*i+1], v.y, a[1][b]);
                                a[2][b] = fma2(w0[2][2*i], v.x, a[2][b]);
                                a[2][b] = fma2(w0[2][2*i+1], v.y, a[2][b]);
                                a[3][b] = fma2(w0[3][2*i], v.x, a[3][b]);
                                a[3][b] = fma2(w0[3][2*i+1], v.y, a[3][b]);
                            }
                        }
#pragma unroll
                        for (int b = 0; b < 4; b++) {
                            float4 sv;
                            sv.x = sumh(a[0][b]); sv.y = sumh(a[1][b]);
                            sv.z = sumh(a[2][b]); sv.w = sumh(a[3][b]);
                            *reinterpret_cast<float4*>(&gw[(wv * 4 + b) * RSTR]) = sv;
                        }
                    }
                }
            }
            BARRIER(1, G0T);
            if (s < TSTEPS) {
                float* sb = in1 + (s & 1) * NB * K1;
#pragma unroll
                for (int k = 0; k < 4; k++) {
                    int c = tid + G0T * k;
                    if (c < 800) {
                        int j = c % 50, b = c / 50;
                        float gi = bias0[j], gf = bias0[50 + j];
                        float gg = bias0[100 + j], go = bias0[150 + j];
#pragma unroll
                        for (int p = 0; p < 4; p++) {
                            const float* gp = g0 + (size_t)(p * 16 + b) * RSTR + j;
                            gi += gp[0]; gf += gp[50]; gg += gp[100]; go += gp[150];
                        }
                        float i_ = fsigmoid(gi), f_ = fsigmoid(gf);
                        float g_ = ftanh(gg),   o_ = fsigmoid(go);
                        float cc = f_ * c0s[k] + i_ * g_;
                        c0s[k] = cc;
                        float h = o_ * ftanh(cc);
                        in0[b * K0 + IIN + j] = h;   // layer0 recurrence (t+1)
                        sb[b * K1 + j] = h;          // layer1 input (t)
                    }
                }
                if (tid < 96)
                    *reinterpret_cast<float2*>(&in0[xb * K0 + 2 * xp]) = xpre;
            }
            BARRIER(3, NTH);
        }
    } else {
        // ================= LAYER-1 GROUP =================
        const int t1 = tid - G0T;
        const bool act = t1 < 200;
        const int q = t1 % 50, ks = t1 / 50;       // rows 4q..4q+3, k slice [28ks,28ks+28)
        ull w1[4][14];
        if (act) {
#pragma unroll
            for (int r = 0; r < 4; r++)
#pragma unroll
                for (int i = 0; i < 14; i++) {
                    int f = ks * 28 + 2 * i;
                    w1[r][i] = pk(wl1(w_ih1, w_hh1, 4 * q + r, f),
                                  wl1(w_ih1, w_hh1, 4 * q + r, f + 1));
                }
        }
        float* gw = g1 + (size_t)(ks * 16) * RSTR + 4 * q;
        float c1s[4] = {0.f, 0.f, 0.f, 0.f};

        for (int s = 0; s <= TSTEPS; s++) {
            if (s >= 1 && act) {
                const float* ib = in1 + ((s - 1) & 1) * NB * K1 + ks * 28;
#pragma unroll
                for (int wv = 0; wv < 8; wv++) {
                    ull a[4][2];
#pragma unroll
                    for (int r = 0; r < 4; r++) { a[r][0] = 0ull; a[r][1] = 0ull; }
#pragma unroll
                    for (int i = 0; i < 7; i++) {
#pragma unroll
                        for (int b = 0; b < 2; b++) {
                            ulonglong2 v = *reinterpret_cast<const ulonglong2*>(
                                &ib[(wv * 2 + b) * K1 + i * 4]);
                            a[0][b] = fma2(w1[0][2*i], v.x, a[0][b]);
                            a[0][b] = fma2(w1[0][2*i+1], v.y, a[0][b]);
                            a[1][b] = fma2(w1[1][2*i], v.x, a[1][b]);
                            a[1][b] = fma2(w1[1][2*i+1], v.y, a[1][b]);
                            a[2][b] = fma2(w1[2][2*i], v.x, a[2][b]);
                            a[2][b] = fma2(w1[2][2*i+1], v.y, a[2][b]);
                            a[3][b] = fma2(w1[3][2*i], v.x, a[3][b]);
                            a[3][b] = fma2(w1[3][2*i+1], v.y, a[3][b]);
                        }
                    }
#pragma unroll
                    for (int b = 0; b < 2; b++) {
                        float4 sv;
                        sv.x = sumh(a[0][b]); sv.y = sumh(a[1][b]);
                        sv.z = sumh(a[2][b]); sv.w = sumh(a[3][b]);
                        *reinterpret_cast<float4*>(&gw[(wv * 2 + b) * RSTR]) = sv;
                    }
                }
            }
            BARRIER(2, NTH - G0T);
            if (s >= 1) {
                float* sb = in1 + (s & 1) * NB * K1;
#pragma unroll
                for (int k = 0; k < 4; k++) {
                    int c = t1 + (NTH - G0T) * k;
                    if (c < 800) {
                        int j = c % 50, b = c / 50;
                        float gi = bias1[j], gf = bias1[50 + j];
                        float gg = bias1[100 + j], go = bias1[150 + j];
#pragma unroll
                        for (int p = 0; p < 4; p++) {
                            const float* gp = g1 + (size_t)(p * 16 + b) * RSTR + j;
                            gi += gp[0]; gf += gp[50]; gg += gp[100]; go += gp[150];
                        }
                        float i_ = fsigmoid(gi), f_ = fsigmoid(gf);
                        float g_ = ftanh(gg),   o_ = fsigmoid(go);
                        float cc = f_ * c1s[k] + i_ * g_;
                        c1s[k] = cc;
                        float h = o_ * ftanh(cc);
                        sb[b * K1 + 56 + j] = h;     // layer1 recurrence
                    }
                }
            }
            BARRIER(3, NTH);
        }
    }
    __syncthreads();

    // head: final h1 = h1(511), written at superstep 512 into buffer (512&1)=0
    if (tid < NB) {
        float acc = b_out[0];
        const float* hb = in1 + tid * K1 + 56;
#pragma unroll
        for (int j = 0; j < HH; j++) acc += w_out[j] * hb[j];
        out[bbase + tid] = fsigmoid(acc);
    }
}

extern "C" void kernel_launch(void* const* d_in, const int* in_sizes, int n_in,
                              void* d_out, int out_size) {
    const float* x     = (const float*)d_in[0];
    const float* w_ih0 = (const float*)d_in[1];
    const float* w_hh0 = (const float*)d_in[2];
    const float* b_ih0 = (const float*)d_in[3];
    const float* b_hh0 = (const float*)d_in[4];
    const float* w_ih1 = (const float*)d_in[5];
    const float* w_hh1 = (const float*)d_in[6];
    const float* b_ih1 = (const float*)d_in[7];
    const float* b_hh1 = (const float*)d_in[8];
    const float* w_out = (const float*)d_in[9];
    const float* b_out = (const float*)d_in[10];
    float* out = (float*)d_out;

    cudaFuncSetAttribute(lstm_kernel, cudaFuncAttributeMaxDynamicSharedMemorySize, SMEM_BYTES);
    lstm_kernel<<<BTOT / NB, NTH, SMEM_BYTES>>>(
        x, w_ih0, w_hh0, b_ih0, b_hh0, w_ih1, w_hh1, b_ih1, b_hh1, w_out, b_out, out);
}

// round 7
// speedup vs baseline: 1.0263x; 1.0263x over previous
#include <cuda_runtime.h>
#include <cstdint>

#define NB 16
#define NTH 640
#define G0T 224          // threads 0..223: layer0 (50 j x 4 ks; 200 active)
                         // threads 224..639: layer1 (50 j x 8 ks; 400 active)
#define HH 50
#define TSTEPS 512
#define IIN 12
#define BTOT 2048

#define IN0S 80          // in0 batch stride: 4 slices x (16 data + 4 skew)
#define IN1S 160         // in1 batch stride: 8 slices x (16 data + 4 skew)
// logical k -> skewed phys index (slice = k>>4 offset by 4 floats each)
#define SK(k) ((k) + 4*((k) >> 4))

typedef unsigned long long ull;

__device__ __forceinline__ ull fma2(ull a, ull b, ull c) {
    ull d;
    asm("fma.rn.f32x2 %0, %1, %2, %3;" : "=l"(d) : "l"(a), "l"(b), "l"(c));
    return d;
}
__device__ __forceinline__ float sumh(ull v) {
    float lo = __uint_as_float((unsigned)(v & 0xffffffffull));
    float hi = __uint_as_float((unsigned)(v >> 32));
    return lo + hi;
}
__device__ __forceinline__ ull pk(float a, float b) {
    return (ull)__float_as_uint(a) | ((ull)__float_as_uint(b) << 32);
}
__device__ __forceinline__ float fsigmoid(float x) {
    float e = __expf(-x);
    return __fdividef(1.0f, 1.0f + e);
}
__device__ __forceinline__ float ftanh(float x) {
    float a = fabsf(x);
    float e = __expf(2.0f * a);
    float r = 1.0f - __fdividef(2.0f, e + 1.0f);
    return copysignf(r, x);
}
// layer0 concat k (64): [x(12)|h0(50)|pad(2)]
__device__ __forceinline__ float wl0(const float* wi, const float* wh, int r, int f) {
    if (f < IIN) return wi[r * IIN + f];
    if (f < IIN + HH) return wh[r * HH + (f - IIN)];
    return 0.f;
}
// layer1 concat k (128): [h0(50)|pad(14)|h1(50)|pad(14)]
__device__ __forceinline__ float wl1(const float* wi, const float* wh, int r, int f) {
    if (f < HH) return wi[r * HH + f];
    if (f >= 64 && f < 64 + HH) return wh[r * HH + (f - 64)];
    return 0.f;
}

__global__ void __launch_bounds__(NTH, 1)
lstm_kernel(const float* __restrict__ x,
            const float* __restrict__ w_ih0, const float* __restrict__ w_hh0,
            const float* __restrict__ b_ih0, const float* __restrict__ b_hh0,
            const float* __restrict__ w_ih1, const float* __restrict__ w_hh1,
            const float* __restrict__ b_ih1, const float* __restrict__ b_hh1,
            const float* __restrict__ w_out, const float* __restrict__ b_out,
            float* __restrict__ out) {
    __shared__ float in0[2 * NB * IN0S];   // [2][NB][80]  x|h0 skewed
    __shared__ float in1[2 * NB * IN1S];   // [2][NB][160] h0|h1 skewed

    const int tid = threadIdx.x;
    const int bbase = blockIdx.x * NB;

    for (int i = tid; i < 2 * NB * IN0S; i += NTH) in0[i] = 0.f;
    for (int i = tid; i < 2 * NB * IN1S; i += NTH) in1[i] = 0.f;
    __syncthreads();
    if (tid < 96) {   // stage x(0) into buffer 0 (k<12 -> no skew)
        int b = tid / 6, p = tid % 6;
        *reinterpret_cast<float2*>(&in0[b * IN0S + 2 * p]) =
            *reinterpret_cast<const float2*>(&x[((size_t)(bbase + b) * TSTEPS) * IIN + 2 * p]);
    }
    __syncthreads();

    if (tid < G0T) {
        // ========== LAYER 0 : unit j, k-slice ks (4 slices of 16) ==========
        const int lane = tid & 31;
        const int j = 8 * (tid >> 5) + (lane >> 2);
        const int ks = lane & 3;
        const bool act = j < HH;

        ull w0[4][8];
        float bq[4];
#pragma unroll
        for (int G = 0; G < 4; G++) {
            int r = j + 50 * G;
#pragma unroll
            for (int i = 0; i < 8; i++) {
                int f = ks * 16 + 2 * i;
                w0[G][i] = act ? pk(wl0(w_ih0, w_hh0, r, f), wl0(w_ih0, w_hh0, r, f + 1)) : 0ull;
            }
            bq[G] = act ? (b_ih0[r] + b_hh0[r]) * 0.25f : 0.f;
        }
        float c0[4] = {0.f, 0.f, 0.f, 0.f};
        const int xb = tid / 6, xp = tid % 6;

        for (int s = 0; s <= TSTEPS; s++) {
            if (s < TSTEPS) {
                float2 xpre;
                if (tid < 96) {
                    int tn = (s + 1 < TSTEPS) ? s + 1 : TSTEPS - 1;
                    xpre = *reinterpret_cast<const float2*>(
                        &x[((size_t)(bbase + xb) * TSTEPS + tn) * IIN + 2 * xp]);
                }
                const float* ib = in0 + (s & 1) * NB * IN0S + ks * 20;
                float* o0 = in0 + ((s + 1) & 1) * NB * IN0S;
                float* o1 = in1 + (s & 1) * NB * IN1S;
#pragma unroll
                for (int g = 0; g < 4; g++) {
                    float fa[4][4];
#pragma unroll
                    for (int bb = 0; bb < 4; bb++) {
                        const float* p = ib + (4 * g + bb) * IN0S;
                        ull t0 = pk(bq[0], 0.f), t1 = pk(bq[1], 0.f);
                        ull t2 = pk(bq[2], 0.f), t3 = pk(bq[3], 0.f);
#pragma unroll
                        for (int i = 0; i < 4; i++) {
                            ulonglong2 v = *reinterpret_cast<const ulonglong2*>(p + 4 * i);
                            t0 = fma2(w0[0][2*i], v.x, t0); t0 = fma2(w0[0][2*i+1], v.y, t0);
                            t1 = fma2(w0[1][2*i], v.x, t1); t1 = fma2(w0[1][2*i+1], v.y, t1);
                            t2 = fma2(w0[2][2*i], v.x, t2); t2 = fma2(w0[2][2*i+1], v.y, t2);
                            t3 = fma2(w0[3][2*i], v.x, t3); t3 = fma2(w0[3][2*i+1], v.y, t3);
                        }
                        fa[0][bb] = sumh(t0); fa[1][bb] = sumh(t1);
                        fa[2][bb] = sumh(t2); fa[3][bb] = sumh(t3);
                    }
                    // reduce-scatter over 4 ks lanes -> lane ks gets batch 4g+ks
                    float fin[4];
#pragma unroll
                    for (int G = 0; G < 4; G++) {
                        float k0 = (ks & 1) ? fa[G][1] : fa[G][0];
                        float s0 = (ks & 1) ? fa[G][0] : fa[G][1];
                        float k1 = (ks & 1) ? fa[G][3] : fa[G][2];
                        float s1 = (ks & 1) ? fa[G][2] : fa[G][3];
                        float r0 = k0 + __shfl_xor_sync(0xffffffffu, s0, 1);
                        float r1 = k1 + __shfl_xor_sync(0xffffffffu, s1, 1);
                        float kk = (ks & 2) ? r1 : r0;
                        float ss = (ks & 2) ? r0 : r1;
                        fin[G] = kk + __shfl_xor_sync(0xffffffffu, ss, 2);
                    }
                    int b = 4 * g + ks;
                    float i_ = fsigmoid(fin[0]), f_ = fsigmoid(fin[1]);
                    float g_ = ftanh(fin[2]),   o_ = fsigmoid(fin[3]);
                    float cc = f_ * c0[g] + i_ * g_;
                    c0[g] = cc;
                    float h = o_ * ftanh(cc);
                    if (act) {
                        o0[b * IN0S + SK(IIN + j)] = h;   // layer0 recurrence (t+1)
                        o1[b * IN1S + SK(j)] = h;         // layer1 input (t)
                    }
                }
                if (tid < 96)
                    *reinterpret_cast<float2*>(&o0[xb * IN0S + 2 * xp]) = xpre;
            }
            __syncthreads();
        }
    } else {
        // ========== LAYER 1 : unit j, k-slice ks (8 slices of 16) ==========
        const int t1 = tid - G0T;
        const int lane = t1 & 31;
        const int j = 4 * (t1 >> 5) + (lane >> 3);
        const int ks = lane & 7;
        const bool act = j < HH;

        ull w1[4][8];
        float bq[4];
#pragma unroll
        for (int G = 0; G < 4; G++) {
            int r = j + 50 * G;
#pragma unroll
            for (int i = 0; i < 8; i++) {
                int f = ks * 16 + 2 * i;
                w1[G][i] = act ? pk(wl1(w_ih1, w_hh1, r, f), wl1(w_ih1, w_hh1, r, f + 1)) : 0ull;
            }
            bq[G] = act ? (b_ih1[r] + b_hh1[r]) * 0.125f : 0.f;
        }
        float c1[4] = {0.f, 0.f, 0.f, 0.f};

        for (int s = 0; s <= TSTEPS; s++) {
            if (s >= 1) {
                const float* ib = in1 + ((s - 1) & 1) * NB * IN1S + ks * 20;
                float* o1 = in1 + (s & 1) * NB * IN1S;
#pragma unroll
                for (int g = 0; g < 4; g++) {
                    float fa[4][4];
#pragma unroll
                    for (int bb = 0; bb < 4; bb++) {
                        const float* p = ib + (4 * g + bb) * IN1S;
                        ull t0 = pk(bq[0], 0.f), t1v = pk(bq[1], 0.f);
                        ull t2 = pk(bq[2], 0.f), t3 = pk(bq[3], 0.f);
#pragma unroll
                        for (int i = 0; i < 4; i++) {
                            ulonglong2 v = *reinterpret_cast<const ulonglong2*>(p + 4 * i);
                            t0  = fma2(w1[0][2*i], v.x, t0);  t0  = fma2(w1[0][2*i+1], v.y, t0);
                            t1v = fma2(w1[1][2*i], v.x, t1v); t1v = fma2(w1[1][2*i+1], v.y, t1v);
                            t2  = fma2(w1[2][2*i], v.x, t2);  t2  = fma2(w1[2][2*i+1], v.y, t2);
                            t3  = fma2(w1[3][2*i], v.x, t3);  t3  = fma2(w1[3][2*i+1], v.y, t3);
                        }
                        fa[0][bb] = sumh(t0);  fa[1][bb] = sumh(t1v);
                        fa[2][bb] = sumh(t2);  fa[3][bb] = sumh(t3);
                    }
                    // reduce-scatter over 8 ks lanes -> lanes ks, ks^4 get batch 4g+(ks&3)
                    float fin[4];
#pragma unroll
                    for (int G = 0; G < 4; G++) {
                        float k0 = (ks & 1) ? fa[G][1] : fa[G][0];
                        float s0 = (ks & 1) ? fa[G][0] : fa[G][1];
                        float k1 = (ks & 1) ? fa[G][3] : fa[G][2];
                        float s1 = (ks & 1) ? fa[G][2] : fa[G][3];
                        float r0 = k0 + __shfl_xor_sync(0xffffffffu, s0, 1);
                        float r1 = k1 + __shfl_xor_sync(0xffffffffu, s1, 1);
                        float kk = (ks & 2) ? r1 : r0;
                        float ss = (ks & 2) ? r0 : r1;
                        float f2 = kk + __shfl_xor_sync(0xffffffffu, ss, 2);
                        fin[G] = f2 + __shfl_xor_sync(0xffffffffu, f2, 4);
                    }
                    int b = 4 * g + (ks & 3);
                    float i_ = fsigmoid(fin[0]), f_ = fsigmoid(fin[1]);
                    float g_ = ftanh(fin[2]),   o_ = fsigmoid(fin[3]);
                    float cc = f_ * c1[g] + i_ * g_;
                    c1[g] = cc;
                    float h = o_ * ftanh(cc);
                    if (act && ks < 4)
                        o1[b * IN1S + SK(64 + j)] = h;    // layer1 recurrence
                }
            }
            __syncthreads();
        }
    }

    // head: h1(511) lives in in1 buffer (512&1)=0, h1 section
    if (tid < NB) {
        float acc = b_out[0];
        const float* hb = in1 + tid * IN1S;
#pragma unroll
        for (int j = 0; j < HH; j++) acc += w_out[j] * hb[SK(64 + j)];
        out[bbase + tid] = fsigmoid(acc);
    }
}

extern "C" void kernel_launch(void* const* d_in, const int* in_sizes, int n_in,
                              void* d_out, int out_size) {
    const float* x     = (const float*)d_in[0];
    const float* w_ih0 = (const float*)d_in[1];
    const float* w_hh0 = (const float*)d_in[2];
    const float* b_ih0 = (const float*)d_in[3];
    const float* b_hh0 = (const float*)d_in[4];
    const float* w_ih1 = (const float*)d_in[5];
    const float* w_hh1 = (const float*)d_in[6];
    const float* b_ih1 = (const float*)d_in[7];
    const float* b_hh1 = (const float*)d_in[8];
    const float* w_out = (const float*)d_in[9];
    const float* b_out = (const float*)d_in[10];
    float* out = (float*)d_out;

    lstm_kernel<<<BTOT / NB, NTH>>>(
        x, w_ih0, w_hh0, b_ih0, b_hh0, w_ih1, w_hh1, b_ih1, b_hh1, w_out, b_out, out);
}

// round 9
// speedup vs baseline: 3.1997x; 3.1178x over previous
#include <cuda_runtime.h>
#include <cstdint>

#define NB 16
#define NTH 416          // 13 warps
#define HH 50
#define TSTEPS 512
#define IIN 12
#define BTOT 2048

#define KP0 68           // I0 row stride (floats): K=64 + 4 pad
#define KP1 132          // I1 row stride: K=128 + 4 pad
#define GS  232          // gate buffer row stride (floats), conflict-free for float2 stores

// smem float offsets
#define I0_OFF 0                           // [2][16*KP0]
#define I1_OFF (2*16*KP0)                  // [2][16*KP1]
#define GB0_OFF (I1_OFF + 2*16*KP1)        // [16][GS]
#define GB1_OFF (GB0_OFF + 16*GS)          // [16][GS]
#define BS0_OFF (GB1_OFF + 16*GS)          // [200]
#define BS1_OFF (BS0_OFF + 200)            // [200]
#define SMEM_FLOATS (BS1_OFF + 200)
#define SMEM_BYTES (SMEM_FLOATS*4)

static __device__ __forceinline__ uint32_t smem_u32(const void* p) {
    uint32_t a;
    asm("{ .reg .u64 t; cvta.to.shared.u64 t, %1; cvt.u32.u64 %0, t; }" : "=r"(a) : "l"(p));
    return a;
}
static __device__ __forceinline__ uint32_t tf32r(float f) {
    uint32_t r; asm("cvt.rna.tf32.f32 %0, %1;" : "=r"(r) : "f"(f)); return r;
}
static __device__ __forceinline__ void ldmx4(uint32_t* a, uint32_t addr) {
    asm volatile("ldmatrix.sync.aligned.m8n8.x4.shared.b16 {%0,%1,%2,%3}, [%4];"
        : "=r"(a[0]), "=r"(a[1]), "=r"(a[2]), "=r"(a[3]) : "r"(addr));
}
static __device__ __forceinline__ void mma8(float* c, const uint32_t* a, uint32_t b0, uint32_t b1) {
    asm volatile("mma.sync.aligned.m16n8k8.row.col.f32.tf32.tf32.f32 "
        "{%0,%1,%2,%3}, {%4,%5,%6,%7}, {%8,%9}, {%0,%1,%2,%3};"
        : "+f"(c[0]), "+f"(c[1]), "+f"(c[2]), "+f"(c[3])
        : "r"(a[0]), "r"(a[1]), "r"(a[2]), "r"(a[3]), "r"(b0), "r"(b1));
}

__device__ __forceinline__ float fsigmoid(float x) {
    float e = __expf(-x);
    return __fdividef(1.0f, 1.0f + e);
}
__device__ __forceinline__ float ftanh(float x) {
    float a = fabsf(x);
    float e = __expf(2.0f * a);
    float r = 1.0f - __fdividef(2.0f, e + 1.0f);
    return copysignf(r, x);
}
// layer0 concat k (64): [x(12)|h0(50)|pad2]
__device__ __forceinline__ float wl0(const float* wi, const float* wh, int r, int f) {
    if (f < IIN) return wi[r * IIN + f];
    if (f < IIN + HH) return wh[r * HH + (f - IIN)];
    return 0.f;
}
// layer1 concat k (128): [h0(50)|pad14|h1(50)|pad14]
__device__ __forceinline__ float wl1(const float* wi, const float* wh, int r, int f) {
    if (f < HH) return wi[r * HH + f];
    if (f >= 64 && f < 64 + HH) return wh[r * HH + (f - 64)];
    return 0.f;
}

__global__ void __launch_bounds__(NTH, 1)
lstm_kernel(const float* __restrict__ x,
            const float* __restrict__ w_ih0, const float* __restrict__ w_hh0,
            const float* __restrict__ b_ih0, const float* __restrict__ b_hh0,
            const float* __restrict__ w_ih1, const float* __restrict__ w_hh1,
            const float* __restrict__ b_ih1, const float* __restrict__ b_hh1,
            const float* __restrict__ w_out, const float* __restrict__ b_out,
            float* __restrict__ out) {
    extern __shared__ float sm[];
    float* I0    = sm + I0_OFF;     // [2][16][KP0]  tf32-rounded [x|h0]
    float* I1    = sm + I1_OFF;     // [2][16][KP1]  tf32-rounded [h0|pad|h1|pad]
    float* GB0   = sm + GB0_OFF;    // [16 batch][GS]  l0 gates
    float* GB1   = sm + GB1_OFF;
    float* bias0 = sm + BS0_OFF;
    float* bias1 = sm + BS1_OFF;

    const int tid  = threadIdx.x;
    const int lane = tid & 31;
    const int w    = tid >> 5;       // warp 0..12
    const int bbase = blockIdx.x * NB;

    for (int i = tid; i < 2 * 16 * KP0; i += NTH) I0[i] = 0.f;
    for (int i = tid; i < 2 * 16 * KP1; i += NTH) I1[i] = 0.f;
    if (tid < 200) {
        bias0[tid] = b_ih0[tid] + b_hh0[tid];
        bias1[tid] = b_ih1[tid] + b_hh1[tid];
    }
    __syncthreads();
    if (tid < 96) {   // stage x(0) into I0 buffer 0 (tf32-rounded)
        int b = tid / 6, p = tid % 6;
        float2 v = *reinterpret_cast<const float2*>(&x[(size_t)(bbase + b) * TSTEPS * IIN + 2 * p]);
        I0[b * KP0 + 2 * p]     = __uint_as_float(tf32r(v.x));
        I0[b * KP0 + 2 * p + 1] = __uint_as_float(tf32r(v.y));
    }

    // ---- resident weight B-fragments ----
    // warp w owns gate ntiles {2w, 2w+1} for both layers (8 gate rows each).
    uint32_t wb0[2][8][2], wb1[2][16][2];
#pragma unroll
    for (int u = 0; u < 2; u++) {
        int nrow = (2 * w + u) * 8 + (lane >> 2);
        bool ok = nrow < 200;
#pragma unroll
        for (int kt = 0; kt < 8; kt++) {
            int k = kt * 8 + (lane & 3);
            wb0[u][kt][0] = tf32r(ok ? wl0(w_ih0, w_hh0, nrow, k)     : 0.f);
            wb0[u][kt][1] = tf32r(ok ? wl0(w_ih0, w_hh0, nrow, k + 4) : 0.f);
        }
#pragma unroll
        for (int kt = 0; kt < 16; kt++) {
            int k = kt * 8 + (lane & 3);
            wb1[u][kt][0] = tf32r(ok ? wl1(w_ih1, w_hh1, nrow, k)     : 0.f);
            wb1[u][kt][1] = tf32r(ok ? wl1(w_ih1, w_hh1, nrow, k + 4) : 0.f);
        }
    }

    // ldmatrix per-lane source: matrix L/8 row L%8 ->
    // batch = (L%8) + 8*((L/8)&1), k-quad = L/16
    const int lrow = (lane & 7) + 8 * ((lane >> 3) & 1);
    const int lkq  = (lane >> 4) & 1;
    const uint32_t a0base = smem_u32(I0) + (uint32_t)(lrow * KP0) * 4u + (uint32_t)lkq * 16u;
    const uint32_t a1base = smem_u32(I1) + (uint32_t)(lrow * KP1) * 4u + (uint32_t)lkq * 16u;

    // D store base: batch = lane/4, gate col = ntile*8 + 2*(lane%3... %4)
    float* g0st = GB0 + (lane >> 2) * GS + 2 * w * 8 + 2 * (lane & 3);
    float* g1st = GB1 + (lane >> 2) * GS + 2 * w * 8 + 2 * (lane & 3);

    float c0st[2] = {0.f, 0.f}, c1st[2] = {0.f, 0.f};
    const int xb = tid / 6, xp = tid % 6;

    for (int s = 0; s <= TSTEPS; s++) {
        float2 xpv;
        const bool dox = (tid < 96) && (s + 1 < TSTEPS);
        if (dox)
            xpv = *reinterpret_cast<const float2*>(
                &x[((size_t)(bbase + xb) * TSTEPS + (s + 1)) * IIN + 2 * xp]);

        // ---- GEMM phase ----
        if (s < TSTEPS) {     // layer0 gates(s)
            float acc[2][4];
#pragma unroll
            for (int u = 0; u < 2; u++)
#pragma unroll
                for (int i = 0; i < 4; i++) acc[u][i] = 0.f;
            uint32_t ab = a0base + (uint32_t)(s & 1) * (16 * KP0 * 4);
#pragma unroll
            for (int kt = 0; kt < 8; kt++) {
                uint32_t a[4];
                ldmx4(a, ab + kt * 32);
                mma8(acc[0], a, wb0[0][kt][0], wb0[0][kt][1]);
                mma8(acc[1], a, wb0[1][kt][0], wb0[1][kt][1]);
            }
#pragma unroll
            for (int u = 0; u < 2; u++) {
                *reinterpret_cast<float2*>(g0st + u * 8)          = make_float2(acc[u][0], acc[u][1]);
                *reinterpret_cast<float2*>(g0st + u * 8 + 8 * GS) = make_float2(acc[u][2], acc[u][3]);
            }
        }
        if (s >= 1) {         // layer1 gates(s-1)
            float acc[2][4];
#pragma unroll
            for (int u = 0; u < 2; u++)
#pragma unroll
                for (int i = 0; i < 4; i++) acc[u][i] = 0.f;
            uint32_t ab = a1base + (uint32_t)((s - 1) & 1) * (16 * KP1 * 4);
#pragma unroll
            for (int kt = 0; kt < 16; kt++) {
                uint32_t a[4];
                ldmx4(a, ab + kt * 32);
                mma8(acc[0], a, wb1[0][kt][0], wb1[0][kt][1]);
                mma8(acc[1], a, wb1[1][kt][0], wb1[1][kt][1]);
            }
#pragma unroll
            for (int u = 0; u < 2; u++) {
                *reinterpret_cast<float2*>(g1st + u * 8)          = make_float2(acc[u][0], acc[u][1]);
                *reinterpret_cast<float2*>(g1st + u * 8 + 8 * GS) = make_float2(acc[u][2], acc[u][3]);
            }
        }
        __syncthreads();

        // ---- update phase ----
        float* I0n = I0 + ((s + 1) & 1) * 16 * KP0;
        float* I1c = I1 + (s & 1) * 16 * KP1;
        if (s < TSTEPS) {
#pragma unroll
            for (int it = 0; it < 2; it++) {
                int p = tid + NTH * it;
                if (p < 800) {
                    int b = p / 50, j = p % 50;
                    const float* gb = GB0 + b * GS + j;
                    float gi = gb[0]   + bias0[j];
                    float gf = gb[50]  + bias0[50 + j];
                    float gg = gb[100] + bias0[100 + j];
                    float go = gb[150] + bias0[150 + j];
                    float i_ = fsigmoid(gi), f_ = fsigmoid(gf);
                    float g_ = ftanh(gg),   o_ = fsigmoid(go);
                    float cc = f_ * c0st[it] + i_ * g_;
                    c0st[it] = cc;
                    float hv = __uint_as_float(tf32r(o_ * ftanh(cc)));
                    I0n[b * KP0 + IIN + j] = hv;   // layer0 recurrence (t+1)
                    I1c[b * KP1 + j]       = hv;   // layer1 input (t)
                }
            }
        }
        if (s >= 1) {
#pragma unroll
            for (int it = 0; it < 2; it++) {
                int p = tid + NTH * it;
                if (p < 800) {
                    int b = p / 50, j = p % 50;
                    const float* gb = GB1 + b * GS + j;
                    float gi = gb[0]   + bias1[j];
                    float gf = gb[50]  + bias1[50 + j];
                    float gg = gb[100] + bias1[100 + j];
                    float go = gb[150] + bias1[150 + j];
                    float i_ = fsigmoid(gi), f_ = fsigmoid(gf);
                    float g_ = ftanh(gg),   o_ = fsigmoid(go);
                    float cc = f_ * c1st[it] + i_ * g_;
                    c1st[it] = cc;
                    I1c[b * KP1 + 64 + j] = __uint_as_float(tf32r(o_ * ftanh(cc)));
                }
            }
        }
        if (dox) {
            I0n[xb * KP0 + 2 * xp]     = __uint_as_float(tf32r(xpv.x));
            I0n[xb * KP0 + 2 * xp + 1] = __uint_as_float(tf32r(xpv.y));
        }
        __syncthreads();
    }

    // head: h1(511) is in I1 buffer (512&1)=0
    if (tid < NB) {
        float acc = b_out[0];
        const float* hb = I1 + tid * KP1 + 64;
#pragma unroll
        for (int j = 0; j < HH; j++) acc += w_out[j] * hb[j];
        out[bbase + tid] = fsigmoid(acc);
    }
}

extern "C" void kernel_launch(void* const* d_in, const int* in_sizes, int n_in,
                              void* d_out, int out_size) {
    const float* x     = (const float*)d_in[0];
    const float* w_ih0 = (const float*)d_in[1];
    const float* w_hh0 = (const float*)d_in[2];
    const float* b_ih0 = (const float*)d_in[3];
    const float* b_hh0 = (const float*)d_in[4];
    const float* w_ih1 = (const float*)d_in[5];
    const float* w_hh1 = (const float*)d_in[6];
    const float* b_ih1 = (const float*)d_in[7];
    const float* b_hh1 = (const float*)d_in[8];
    const float* w_out = (const float*)d_in[9];
    const float* b_out = (const float*)d_in[10];
    float* out = (float*)d_out;

    cudaFuncSetAttribute(lstm_kernel, cudaFuncAttributeMaxDynamicSharedMemorySize, SMEM_BYTES);
    lstm_kernel<<<BTOT / NB, NTH, SMEM_BYTES>>>(
        x, w_ih0, w_hh0, b_ih0, b_hh0, w_ih1, w_hh1, b_ih1, b_hh1, w_out, b_out, out);
}

// round 10
// speedup vs baseline: 3.8460x; 1.2020x over previous
#include <cuda_runtime.h>
#include <cstdint>

#define NB 16
#define NTH 416          // 13 warps
#define HH 50
#define TSTEPS 512
#define IIN 12
#define BTOT 2048

#define KP0 68           // I0 row stride (floats): K=64 + 4 pad
#define KP1 108          // I1 row stride: K=104 + 4 pad
#define H1OFF 52         // h1 offset inside l1 concat input
#define GS  232          // gate buffer row stride (floats)

// smem float offsets
#define I0_OFF 0                           // [2][16*KP0]
#define I1_OFF (2*16*KP0)                  // [2][16*KP1]
#define GB0_OFF (I1_OFF + 2*16*KP1)        // [16][GS]
#define GB1_OFF (GB0_OFF + 16*GS)          // [16][GS]
#define BS0_OFF (GB1_OFF + 16*GS)          // [200]
#define BS1_OFF (BS0_OFF + 200)            // [200]
#define SMEM_FLOATS (BS1_OFF + 200)
#define SMEM_BYTES (SMEM_FLOATS*4)

static __device__ __forceinline__ uint32_t smem_u32(const void* p) {
    uint32_t a;
    asm("{ .reg .u64 t; cvta.to.shared.u64 t, %1; cvt.u32.u64 %0, t; }" : "=r"(a) : "l"(p));
    return a;
}
static __device__ __forceinline__ uint32_t tf32r(float f) {
    uint32_t r; asm("cvt.rna.tf32.f32 %0, %1;" : "=r"(r) : "f"(f)); return r;
}
static __device__ __forceinline__ void ldmx4(uint32_t* a, uint32_t addr) {
    asm volatile("ldmatrix.sync.aligned.m8n8.x4.shared.b16 {%0,%1,%2,%3}, [%4];"
        : "=r"(a[0]), "=r"(a[1]), "=r"(a[2]), "=r"(a[3]) : "r"(addr));
}
static __device__ __forceinline__ void mma8(float* c, const uint32_t* a, uint32_t b0, uint32_t b1) {
    asm volatile("mma.sync.aligned.m16n8k8.row.col.f32.tf32.tf32.f32 "
        "{%0,%1,%2,%3}, {%4,%5,%6,%7}, {%8,%9}, {%0,%1,%2,%3};"
        : "+f"(c[0]), "+f"(c[1]), "+f"(c[2]), "+f"(c[3])
        : "r"(a[0]), "r"(a[1]), "r"(a[2]), "r"(a[3]), "r"(b0), "r"(b1));
}

__device__ __forceinline__ float tanha(float x) {
    float r; asm("tanh.approx.f32 %0, %1;" : "=f"(r) : "f"(x)); return r;
}
__device__ __forceinline__ float fsigmoid(float x) {
    return fmaf(0.5f, tanha(0.5f * x), 0.5f);
}
// layer0 concat k (64): [x(12)|h0(50)|pad2]
__device__ __forceinline__ float wl0(const float* wi, const float* wh, int r, int f) {
    if (f < IIN) return wi[r * IIN + f];
    if (f < IIN + HH) return wh[r * HH + (f - IIN)];
    return 0.f;
}
// layer1 concat k (104): [h0(50)|pad2|h1(50)|pad2]
__device__ __forceinline__ float wl1(const float* wi, const float* wh, int r, int f) {
    if (f < HH) return wi[r * HH + f];
    if (f >= H1OFF && f < H1OFF + HH) return wh[r * HH + (f - H1OFF)];
    return 0.f;
}

__global__ void __launch_bounds__(NTH, 1)
lstm_kernel(const float* __restrict__ x,
            const float* __restrict__ w_ih0, const float* __restrict__ w_hh0,
            const float* __restrict__ b_ih0, const float* __restrict__ b_hh0,
            const float* __restrict__ w_ih1, const float* __restrict__ w_hh1,
            const float* __restrict__ b_ih1, const float* __restrict__ b_hh1,
            const float* __restrict__ w_out, const float* __restrict__ b_out,
            float* __restrict__ out) {
    extern __shared__ float sm[];
    float* I0    = sm + I0_OFF;     // [2][16][KP0]
    float* I1    = sm + I1_OFF;     // [2][16][KP1]
    float* GB0   = sm + GB0_OFF;
    float* GB1   = sm + GB1_OFF;
    float* bias0 = sm + BS0_OFF;
    float* bias1 = sm + BS1_OFF;

    const int tid  = threadIdx.x;
    const int lane = tid & 31;
    const int w    = tid >> 5;
    const int bbase = blockIdx.x * NB;

    for (int i = tid; i < 2 * 16 * KP0; i += NTH) I0[i] = 0.f;
    for (int i = tid; i < 2 * 16 * KP1; i += NTH) I1[i] = 0.f;
    if (tid < 200) {
        bias0[tid] = b_ih0[tid] + b_hh0[tid];
        bias1[tid] = b_ih1[tid] + b_hh1[tid];
    }
    __syncthreads();
    if (tid < 96) {   // stage x(0)
        int b = tid / 6, p = tid % 6;
        float2 v = *reinterpret_cast<const float2*>(&x[(size_t)(bbase + b) * TSTEPS * IIN + 2 * p]);
        I0[b * KP0 + 2 * p]     = __uint_as_float(tf32r(v.x));
        I0[b * KP0 + 2 * p + 1] = __uint_as_float(tf32r(v.y));
    }

    // ---- resident weight B-fragments: warp w owns gate ntiles {2w, 2w+1} ----
    uint32_t wb0[2][8][2], wb1[2][13][2];
#pragma unroll
    for (int u = 0; u < 2; u++) {
        int nrow = (2 * w + u) * 8 + (lane >> 2);
        bool ok = nrow < 200;
#pragma unroll
        for (int kt = 0; kt < 8; kt++) {
            int k = kt * 8 + (lane & 3);
            wb0[u][kt][0] = tf32r(ok ? wl0(w_ih0, w_hh0, nrow, k)     : 0.f);
            wb0[u][kt][1] = tf32r(ok ? wl0(w_ih0, w_hh0, nrow, k + 4) : 0.f);
        }
#pragma unroll
        for (int kt = 0; kt < 13; kt++) {
            int k = kt * 8 + (lane & 3);
            wb1[u][kt][0] = tf32r(ok ? wl1(w_ih1, w_hh1, nrow, k)     : 0.f);
            wb1[u][kt][1] = tf32r(ok ? wl1(w_ih1, w_hh1, nrow, k + 4) : 0.f);
        }
    }

    const int lrow = (lane & 7) + 8 * ((lane >> 3) & 1);
    const int lkq  = (lane >> 4) & 1;
    const uint32_t a0base = smem_u32(I0) + (uint32_t)(lrow * KP0) * 4u + (uint32_t)lkq * 16u;
    const uint32_t a1base = smem_u32(I1) + (uint32_t)(lrow * KP1) * 4u + (uint32_t)lkq * 16u;

    float* g0st = GB0 + (lane >> 2) * GS + 2 * w * 8 + 2 * (lane & 3);
    float* g1st = GB1 + (lane >> 2) * GS + 2 * w * 8 + 2 * (lane & 3);

    float c0st[2] = {0.f, 0.f}, c1st[2] = {0.f, 0.f};
    const int xb = tid / 6, xp = tid % 6;

    for (int s = 0; s <= TSTEPS; s++) {
        float2 xpv;
        const bool dox = (tid < 96) && (s + 1 < TSTEPS);
        if (dox)
            xpv = *reinterpret_cast<const float2*>(
                &x[((size_t)(bbase + xb) * TSTEPS + (s + 1)) * IIN + 2 * xp]);

        // ---- GEMM phase ----
        if (s < TSTEPS) {     // layer0 gates(s)
            float acc[2][4];
#pragma unroll
            for (int u = 0; u < 2; u++)
#pragma unroll
                for (int i = 0; i < 4; i++) acc[u][i] = 0.f;
            uint32_t ab = a0base + (uint32_t)(s & 1) * (16 * KP0 * 4);
#pragma unroll
            for (int kt = 0; kt < 8; kt++) {
                uint32_t a[4];
                ldmx4(a, ab + kt * 32);
                mma8(acc[0], a, wb0[0][kt][0], wb0[0][kt][1]);
                mma8(acc[1], a, wb0[1][kt][0], wb0[1][kt][1]);
            }
#pragma unroll
            for (int u = 0; u < 2; u++) {
                *reinterpret_cast<float2*>(g0st + u * 8)          = make_float2(acc[u][0], acc[u][1]);
                *reinterpret_cast<float2*>(g0st + u * 8 + 8 * GS) = make_float2(acc[u][2], acc[u][3]);
            }
        }
        if (s >= 1) {         // layer1 gates(s-1): split even/odd kt acc chains
            float accA[2][4], accB[2][4];
#pragma unroll
            for (int u = 0; u < 2; u++)
#pragma unroll
                for (int i = 0; i < 4; i++) { accA[u][i] = 0.f; accB[u][i] = 0.f; }
            uint32_t ab = a1base + (uint32_t)((s - 1) & 1) * (16 * KP1 * 4);
#pragma unroll
            for (int kt = 0; kt < 13; kt++) {
                uint32_t a[4];
                ldmx4(a, ab + kt * 32);
                if (kt & 1) {
                    mma8(accB[0], a, wb1[0][kt][0], wb1[0][kt][1]);
                    mma8(accB[1], a, wb1[1][kt][0], wb1[1][kt][1]);
                } else {
                    mma8(accA[0], a, wb1[0][kt][0], wb1[0][kt][1]);
                    mma8(accA[1], a, wb1[1][kt][0], wb1[1][kt][1]);
                }
            }
#pragma unroll
            for (int u = 0; u < 2; u++) {
                float2 lo = make_float2(accA[u][0] + accB[u][0], accA[u][1] + accB[u][1]);
                float2 hi = make_float2(accA[u][2] + accB[u][2], accA[u][3] + accB[u][3]);
                *reinterpret_cast<float2*>(g1st + u * 8)          = lo;
                *reinterpret_cast<float2*>(g1st + u * 8 + 8 * GS) = hi;
            }
        }
        __syncthreads();

        // ---- update phase ----
        float* I0n = I0 + ((s + 1) & 1) * 16 * KP0;
        float* I1c = I1 + (s & 1) * 16 * KP1;
        if (s < TSTEPS) {
#pragma unroll
            for (int it = 0; it < 2; it++) {
                int p = tid + NTH * it;
                if (p < 800) {
                    int b = p / 50, j = p % 50;
                    const float* gb = GB0 + b * GS + j;
                    float gi = gb[0]   + bias0[j];
                    float gf = gb[50]  + bias0[50 + j];
                    float gg = gb[100] + bias0[100 + j];
                    float go = gb[150] + bias0[150 + j];
                    float i_ = fsigmoid(gi), f_ = fsigmoid(gf);
                    float g_ = tanha(gg),   o_ = fsigmoid(go);
                    float cc = f_ * c0st[it] + i_ * g_;
                    c0st[it] = cc;
                    float hv = __uint_as_float(tf32r(o_ * tanha(cc)));
                    I0n[b * KP0 + IIN + j] = hv;   // layer0 recurrence (t+1)
                    I1c[b * KP1 + j]       = hv;   // layer1 input (t)
                }
            }
        }
        if (s >= 1) {
#pragma unroll
            for (int it = 0; it < 2; it++) {
                int p = tid + NTH * it;
                if (p < 800) {
                    int b = p / 50, j = p % 50;
                    const float* gb = GB1 + b * GS + j;
                    float gi = gb[0]   + bias1[j];
                    float gf = gb[50]  + bias1[50 + j];
                    float gg = gb[100] + bias1[100 + j];
                    float go = gb[150] + bias1[150 + j];
                    float i_ = fsigmoid(gi), f_ = fsigmoid(gf);
                    float g_ = tanha(gg),   o_ = fsigmoid(go);
                    float cc = f_ * c1st[it] + i_ * g_;
                    c1st[it] = cc;
                    I1c[b * KP1 + H1OFF + j] = __uint_as_float(tf32r(o_ * tanha(cc)));
                }
            }
        }
        if (dox) {
            I0n[xb * KP0 + 2 * xp]     = __uint_as_float(tf32r(xpv.x));
            I0n[xb * KP0 + 2 * xp + 1] = __uint_as_float(tf32r(xpv.y));
        }
        __syncthreads();
    }

    // head: h1(511) is in I1 buffer (512&1)=0
    if (tid < NB) {
        float acc = b_out[0];
        const float* hb = I1 + tid * KP1 + H1OFF;
#pragma unroll
        for (int j = 0; j < HH; j++) acc += w_out[j] * hb[j];
        float e = __expf(-acc);
        out[bbase + tid] = __fdividef(1.0f, 1.0f + e);
    }
}

extern "C" void kernel_launch(void* const* d_in, const int* in_sizes, int n_in,
                              void* d_out, int out_size) {
    const float* x     = (const float*)d_in[0];
    const float* w_ih0 = (const float*)d_in[1];
    const float* w_hh0 = (const float*)d_in[2];
    const float* b_ih0 = (const float*)d_in[3];
    const float* b_hh0 = (const float*)d_in[4];
    const float* w_ih1 = (const float*)d_in[5];
    const float* w_hh1 = (const float*)d_in[6];
    const float* b_ih1 = (const float*)d_in[7];
    const float* b_hh1 = (const float*)d_in[8];
    const float* w_out = (const float*)d_in[9];
    const float* b_out = (const float*)d_in[10];
    float* out = (float*)d_out;

    cudaFuncSetAttribute(lstm_kernel, cudaFuncAttributeMaxDynamicSharedMemorySize, SMEM_BYTES);
    lstm_kernel<<<BTOT / NB, NTH, SMEM_BYTES>>>(
        x, w_ih0, w_hh0, b_ih0, b_hh0, w_ih1, w_hh1, b_ih1, b_hh1, w_out, b_out, out);
}

// round 11
// speedup vs baseline: 5.6672x; 1.4735x over previous
#include <cuda_runtime.h>
#include <cstdint>

#define NB 16
#define NTH 512          // 16 warps: 0-6 layer0, 7-15 layer1
#define HH 50
#define TSTEPS 512
#define IIN 12
#define BTOT 2048

#define KP0 68           // I0 row stride (floats): K=64 + 4 pad
#define KP1 108          // I1 row stride: K=104 + 4 pad
#define H1OFF 52         // h1 offset inside l1 concat input

static __device__ __forceinline__ uint32_t smem_u32(const void* p) {
    uint32_t a;
    asm("{ .reg .u64 t; cvta.to.shared.u64 t, %1; cvt.u32.u64 %0, t; }" : "=r"(a) : "l"(p));
    return a;
}
static __device__ __forceinline__ uint32_t tf32r(float f) {
    uint32_t r; asm("cvt.rna.tf32.f32 %0, %1;" : "=r"(r) : "f"(f)); return r;
}
static __device__ __forceinline__ void ldmx4(uint32_t* a, uint32_t addr) {
    asm volatile("ldmatrix.sync.aligned.m8n8.x4.shared.b16 {%0,%1,%2,%3}, [%4];"
        : "=r"(a[0]), "=r"(a[1]), "=r"(a[2]), "=r"(a[3]) : "r"(addr));
}
static __device__ __forceinline__ void mma8(float* c, const uint32_t* a, uint32_t b0, uint32_t b1) {
    asm volatile("mma.sync.aligned.m16n8k8.row.col.f32.tf32.tf32.f32 "
        "{%0,%1,%2,%3}, {%4,%5,%6,%7}, {%8,%9}, {%0,%1,%2,%3};"
        : "+f"(c[0]), "+f"(c[1]), "+f"(c[2]), "+f"(c[3])
        : "r"(a[0]), "r"(a[1]), "r"(a[2]), "r"(a[3]), "r"(b0), "r"(b1));
}
__device__ __forceinline__ float tanha(float x) {
    float r; asm("tanh.approx.f32 %0, %1;" : "=f"(r) : "f"(x)); return r;
}
__device__ __forceinline__ float fsigmoid(float x) {
    return fmaf(0.5f, tanha(0.5f * x), 0.5f);
}
// permuted gate rows: row' = 4*j + gate  <->  original row = j + 50*gate
static __device__ __forceinline__ int orow(int rp) { return (rp >> 2) + 50 * (rp & 3); }
// layer0 concat k (64): [x(12)|h0(50)|pad2]
__device__ __forceinline__ float wl0(const float* wi, const float* wh, int r, int f) {
    if (f < IIN) return wi[r * IIN + f];
    if (f < IIN + HH) return wh[r * HH + (f - IIN)];
    return 0.f;
}
// layer1 concat k (104): [h0(50)|pad2|h1(50)|pad2]
__device__ __forceinline__ float wl1(const float* wi, const float* wh, int r, int f) {
    if (f < HH) return wi[r * HH + f];
    if (f >= H1OFF && f < H1OFF + HH) return wh[r * HH + (f - H1OFF)];
    return 0.f;
}

__global__ void __launch_bounds__(NTH, 1)
lstm_kernel(const float* __restrict__ x,
            const float* __restrict__ w_ih0, const float* __restrict__ w_hh0,
            const float* __restrict__ b_ih0, const float* __restrict__ b_hh0,
            const float* __restrict__ w_ih1, const float* __restrict__ w_hh1,
            const float* __restrict__ b_ih1, const float* __restrict__ b_hh1,
            const float* __restrict__ w_out, const float* __restrict__ b_out,
            float* __restrict__ out) {
    __shared__ float I0[2 * 16 * KP0];
    __shared__ float I1[2 * 16 * KP1];

    const int tid  = threadIdx.x;
    const int lane = tid & 31;
    const int w    = tid >> 5;
    const int bbase = blockIdx.x * NB;

    for (int i = tid; i < 2 * 16 * KP0; i += NTH) I0[i] = 0.f;
    for (int i = tid; i < 2 * 16 * KP1; i += NTH) I1[i] = 0.f;
    __syncthreads();
    if (tid < 96) {   // stage x(0)
        int b = tid / 6, p = tid % 6;
        float2 v = *reinterpret_cast<const float2*>(&x[(size_t)(bbase + b) * TSTEPS * IIN + 2 * p]);
        I0[b * KP0 + 2 * p]     = __uint_as_float(tf32r(v.x));
        I0[b * KP0 + 2 * p + 1] = __uint_as_float(tf32r(v.y));
    }
    __syncthreads();

    // ldmatrix per-lane source address components (same for both layers)
    const int lrow = (lane & 7) + 8 * ((lane >> 3) & 1);
    const int lkq  = (lane >> 4) & 1;
    const int m    = lane & 3;
    const int bofs = (lane >> 2) + 8 * (m & 1);   // batch this lane finalizes

    if (w < 7) {
        // ================= LAYER-0 GROUP: warp w owns ntiles 4w..4w+3 =================
        uint32_t wb[4][8][2];
        float bf[4][2];
#pragma unroll
        for (int u = 0; u < 4; u++) {
            int t = 4 * w + u;
            int nr = t * 8 + (lane >> 2);
            bool ok = nr < 200;
            int org = ok ? orow(nr) : 0;
#pragma unroll
            for (int kt = 0; kt < 8; kt++) {
                int k = kt * 8 + m;
                wb[u][kt][0] = tf32r(ok ? wl0(w_ih0, w_hh0, org, k)     : 0.f);
                wb[u][kt][1] = tf32r(ok ? wl0(w_ih0, w_hh0, org, k + 4) : 0.f);
            }
            int c0 = t * 8 + 2 * m;
            bf[u][0] = (c0 < 200)     ? (b_ih0[orow(c0)]     + b_hh0[orow(c0)])     : 0.f;
            bf[u][1] = (c0 + 1 < 200) ? (b_ih0[orow(c0 + 1)] + b_hh0[orow(c0 + 1)]) : 0.f;
        }
        const uint32_t abase = smem_u32(I0) + (uint32_t)(lrow * KP0) * 4u + (uint32_t)lkq * 16u;
        float cst[4] = {0.f, 0.f, 0.f, 0.f};
        const int xb = tid / 6, xp = tid % 6;

        for (int s = 0; s <= TSTEPS; s++) {
            if (s < TSTEPS) {
                float2 xpv;
                const bool dox = (tid < 96) && (s + 1 < TSTEPS);
                if (dox)
                    xpv = *reinterpret_cast<const float2*>(
                        &x[((size_t)(bbase + xb) * TSTEPS + (s + 1)) * IIN + 2 * xp]);

                float acc[4][4];
#pragma unroll
                for (int u = 0; u < 4; u++) {
                    acc[u][0] = bf[u][0]; acc[u][1] = bf[u][1];
                    acc[u][2] = bf[u][0]; acc[u][3] = bf[u][1];
                }
                uint32_t ab = abase + (uint32_t)(s & 1) * (16 * KP0 * 4);
#pragma unroll
                for (int kt = 0; kt < 8; kt++) {
                    uint32_t a[4];
                    ldmx4(a, ab + kt * 32);
#pragma unroll
                    for (int u = 0; u < 4; u++)
                        mma8(acc[u], a, wb[u][kt][0], wb[u][kt][1]);
                }
                // fused update
                float* I0n = I0 + ((s + 1) & 1) * 16 * KP0;
                float* I1c = I1 + (s & 1) * 16 * KP1;
#pragma unroll
                for (int u = 0; u < 4; u++) {
                    float t0 = __shfl_xor_sync(0xffffffffu, (m & 1) ? acc[u][0] : acc[u][2], 1);
                    float t1 = __shfl_xor_sync(0xffffffffu, (m & 1) ? acc[u][1] : acc[u][3], 1);
                    float gi, gf, gg, go;
                    if (!(m & 1)) { gi = acc[u][0]; gf = acc[u][1]; gg = t0; go = t1; }
                    else          { gi = t0;        gf = t1;        gg = acc[u][2]; go = acc[u][3]; }
                    int j = 2 * (4 * w + u) + (m >> 1);
                    if (j < HH) {
                        float i_ = fsigmoid(gi), f_ = fsigmoid(gf);
                        float g_ = tanha(gg),   o_ = fsigmoid(go);
                        float cc = f_ * cst[u] + i_ * g_;
                        cst[u] = cc;
                        float hv = __uint_as_float(tf32r(o_ * tanha(cc)));
                        I0n[bofs * KP0 + IIN + j] = hv;   // layer0 recurrence (t+1)
                        I1c[bofs * KP1 + j]       = hv;   // layer1 input (t)
                    }
                }
                if (dox) {
                    I0n[xb * KP0 + 2 * xp]     = __uint_as_float(tf32r(xpv.x));
                    I0n[xb * KP0 + 2 * xp + 1] = __uint_as_float(tf32r(xpv.y));
                }
            }
            __syncthreads();
        }
    } else {
        // ================= LAYER-1 GROUP: warp (w-7) owns ntiles 3i..3i+2 =================
        const int i1 = w - 7;
        uint32_t wb[3][13][2];
        float bf[3][2];
#pragma unroll
        for (int u = 0; u < 3; u++) {
            int t = 3 * i1 + u;
            int nr = t * 8 + (lane >> 2);
            bool ok = nr < 200;
            int org = ok ? orow(nr) : 0;
#pragma unroll
            for (int kt = 0; kt < 13; kt++) {
                int k = kt * 8 + m;
                wb[u][kt][0] = tf32r(ok ? wl1(w_ih1, w_hh1, org, k)     : 0.f);
                wb[u][kt][1] = tf32r(ok ? wl1(w_ih1, w_hh1, org, k + 4) : 0.f);
            }
            int c0 = t * 8 + 2 * m;
            bf[u][0] = (c0 < 200)     ? (b_ih1[orow(c0)]     + b_hh1[orow(c0)])     : 0.f;
            bf[u][1] = (c0 + 1 < 200) ? (b_ih1[orow(c0 + 1)] + b_hh1[orow(c0 + 1)]) : 0.f;
        }
        const uint32_t abase = smem_u32(I1) + (uint32_t)(lrow * KP1) * 4u + (uint32_t)lkq * 16u;
        float cst[3] = {0.f, 0.f, 0.f};

        for (int s = 0; s <= TSTEPS; s++) {
            if (s >= 1) {
                float acc[3][4];
#pragma unroll
                for (int u = 0; u < 3; u++) {
                    acc[u][0] = bf[u][0]; acc[u][1] = bf[u][1];
                    acc[u][2] = bf[u][0]; acc[u][3] = bf[u][1];
                }
                uint32_t ab = abase + (uint32_t)((s - 1) & 1) * (16 * KP1 * 4);
#pragma unroll
                for (int kt = 0; kt < 13; kt++) {
                    uint32_t a[4];
                    ldmx4(a, ab + kt * 32);
#pragma unroll
                    for (int u = 0; u < 3; u++)
                        mma8(acc[u], a, wb[u][kt][0], wb[u][kt][1]);
                }
                float* I1c = I1 + (s & 1) * 16 * KP1;
#pragma unroll
                for (int u = 0; u < 3; u++) {
                    float t0 = __shfl_xor_sync(0xffffffffu, (m & 1) ? acc[u][0] : acc[u][2], 1);
                    float t1 = __shfl_xor_sync(0xffffffffu, (m & 1) ? acc[u][1] : acc[u][3], 1);
                    float gi, gf, gg, go;
                    if (!(m & 1)) { gi = acc[u][0]; gf = acc[u][1]; gg = t0; go = t1; }
                    else          { gi = t0;        gf = t1;        gg = acc[u][2]; go = acc[u][3]; }
                    int j = 2 * (3 * i1 + u) + (m >> 1);
                    if (j < HH) {
                        float i_ = fsigmoid(gi), f_ = fsigmoid(gf);
                        float g_ = tanha(gg),   o_ = fsigmoid(go);
                        float cc = f_ * cst[u] + i_ * g_;
                        cst[u] = cc;
                        I1c[bofs * KP1 + H1OFF + j] = __uint_as_float(tf32r(o_ * tanha(cc)));
                    }
                }
            }
            __syncthreads();
        }
    }

    // head: h1(511) is in I1 buffer (512&1)=0
    if (tid < NB) {
        float acc = b_out[0];
        const float* hb = I1 + tid * KP1 + H1OFF;
#pragma unroll
        for (int j = 0; j < HH; j++) acc += w_out[j] * hb[j];
        float e = __expf(-acc);
        out[bbase + tid] = __fdividef(1.0f, 1.0f + e);
    }
}

extern "C" void kernel_launch(void* const* d_in, const int* in_sizes, int n_in,
                              void* d_out, int out_size) {
    const float* x     = (const float*)d_in[0];
    const float* w_ih0 = (const float*)d_in[1];
    const float* w_hh0 = (const float*)d_in[2];
    const float* b_ih0 = (const float*)d_in[3];
    const float* b_hh0 = (const float*)d_in[4];
    const float* w_ih1 = (const float*)d_in[5];
    const float* w_hh1 = (const float*)d_in[6];
    const float* b_ih1 = (const float*)d_in[7];
    const float* b_hh1 = (const float*)d_in[8];
    const float* w_out = (const float*)d_in[9];
    const float* b_out = (const float*)d_in[10];
    float* out = (float*)d_out;

    lstm_kernel<<<BTOT / NB, NTH>>>(
        x, w_ih0, w_hh0, b_ih0, b_hh0, w_ih1, w_hh1, b_ih1, b_hh1, w_out, b_out, out);
}

// round 14
// speedup vs baseline: 7.8327x; 1.3821x over previous
#include <cuda_runtime.h>
#include <cuda_fp16.h>
#include <cstdint>

#define NB 16
#define NTH 512          // 16 warps: 0-6 layer0, 7-15 layer1
#define HH 50
#define TSTEPS 512
#define IIN 12
#define BTOT 2048

#define KP0H 72          // I0 row stride in halves: K=64 + 8 pad (144B ≡ 16 mod 128)
#define KP1H 120         // I1 row stride in halves: K=112 + 8 pad (240B ≡ 112 mod 128)
#define H1OFF 56         // h1 offset (halves) inside l1 concat input [h0(50)|pad6|h1(50)|pad6]

static __device__ __forceinline__ uint32_t smem_u32(const void* p) {
    uint32_t a;
    asm("{ .reg .u64 t; cvta.to.shared.u64 t, %1; cvt.u32.u64 %0, t; }" : "=r"(a) : "l"(p));
    return a;
}
static __device__ __forceinline__ uint32_t h2pack(float a, float b) {
    __half2 h = __halves2half2(__float2half_rn(a), __float2half_rn(b));
    return *reinterpret_cast<uint32_t*>(&h);
}
static __device__ __forceinline__ void ldmx4(uint32_t* a, uint32_t addr) {
    asm volatile("ldmatrix.sync.aligned.m8n8.x4.shared.b16 {%0,%1,%2,%3}, [%4];"
        : "=r"(a[0]), "=r"(a[1]), "=r"(a[2]), "=r"(a[3]) : "r"(addr));
}
static __device__ __forceinline__ void mma16(float* c, const uint32_t* a, uint32_t b0, uint32_t b1) {
    asm volatile("mma.sync.aligned.m16n8k16.row.col.f32.f16.f16.f32 "
        "{%0,%1,%2,%3}, {%4,%5,%6,%7}, {%8,%9}, {%0,%1,%2,%3};"
        : "+f"(c[0]), "+f"(c[1]), "+f"(c[2]), "+f"(c[3])
        : "r"(a[0]), "r"(a[1]), "r"(a[2]), "r"(a[3]), "r"(b0), "r"(b1));
}
__device__ __forceinline__ float tanha(float x) {
    float r; asm("tanh.approx.f32 %0, %1;" : "=f"(r) : "f"(x)); return r;
}
__device__ __forceinline__ float fsigmoid(float x) {
    return fmaf(0.5f, tanha(0.5f * x), 0.5f);
}
// permuted gate rows: row' = 4*j + gate  <->  original row = j + 50*gate
static __device__ __forceinline__ int orow(int rp) { return (rp >> 2) + 50 * (rp & 3); }
// layer0 concat k (64): [x(12)|h0(50)|pad2]
__device__ __forceinline__ float wl0(const float* wi, const float* wh, int r, int f) {
    if (f < IIN) return wi[r * IIN + f];
    if (f < IIN + HH) return wh[r * HH + (f - IIN)];
    return 0.f;
}
// layer1 concat k (112): [h0(50)|pad6|h1(50)|pad6]
__device__ __forceinline__ float wl1(const float* wi, const float* wh, int r, int f) {
    if (f < HH) return wi[r * HH + f];
    if (f >= H1OFF && f < H1OFF + HH) return wh[r * HH + (f - H1OFF)];
    return 0.f;
}

__global__ void __launch_bounds__(NTH, 1)
lstm_kernel(const float* __restrict__ x,
            const float* __restrict__ w_ih0, const float* __restrict__ w_hh0,
            const float* __restrict__ b_ih0, const float* __restrict__ b_hh0,
            const float* __restrict__ w_ih1, const float* __restrict__ w_hh1,
            const float* __restrict__ b_ih1, const float* __restrict__ b_hh1,
            const float* __restrict__ w_out, const float* __restrict__ b_out,
            float* __restrict__ out) {
    __shared__ __half I0[2 * 16 * KP0H];
    __shared__ __half I1[2 * 16 * KP1H];

    const int tid  = threadIdx.x;
    const int lane = tid & 31;
    const int w    = tid >> 5;
    const int bbase = blockIdx.x * NB;

    for (int i = tid; i < 2 * 16 * KP0H; i += NTH) I0[i] = __float2half(0.f);
    for (int i = tid; i < 2 * 16 * KP1H; i += NTH) I1[i] = __float2half(0.f);
    __syncthreads();
    if (tid < 96) {   // stage x(0)
        int b = tid / 6, p = tid % 6;
        float2 v = *reinterpret_cast<const float2*>(&x[(size_t)(bbase + b) * TSTEPS * IIN + 2 * p]);
        *reinterpret_cast<__half2*>(&I0[b * KP0H + 2 * p]) =
            __halves2half2(__float2half_rn(v.x), __float2half_rn(v.y));
    }
    __syncthreads();

    // ldmatrix per-lane source address components
    const int lrow = (lane & 7) + 8 * ((lane >> 3) & 1);
    const int lkq  = (lane >> 4) & 1;
    const int m    = lane & 3;
    const int bofs = (lane >> 2) + 8 * (m & 1);   // batch this lane finalizes

    if (w < 7) {
        // ================= LAYER-0 GROUP: warp w owns ntiles 4w..4w+3 =================
        uint32_t wb[4][4][2];
        float bf[4][2];
#pragma unroll
        for (int u = 0; u < 4; u++) {
            int t = 4 * w + u;
            int nr = t * 8 + (lane >> 2);
            bool ok = nr < 200;
            int org = ok ? orow(nr) : 0;
#pragma unroll
            for (int kt = 0; kt < 4; kt++) {
                int k0 = kt * 16 + 2 * m;
                wb[u][kt][0] = ok ? h2pack(wl0(w_ih0, w_hh0, org, k0),
                                           wl0(w_ih0, w_hh0, org, k0 + 1)) : 0u;
                wb[u][kt][1] = ok ? h2pack(wl0(w_ih0, w_hh0, org, k0 + 8),
                                           wl0(w_ih0, w_hh0, org, k0 + 9)) : 0u;
            }
            int c0 = t * 8 + 2 * m;
            bf[u][0] = (c0 < 200)     ? (b_ih0[orow(c0)]     + b_hh0[orow(c0)])     : 0.f;
            bf[u][1] = (c0 + 1 < 200) ? (b_ih0[orow(c0 + 1)] + b_hh0[orow(c0 + 1)]) : 0.f;
        }
        const uint32_t abase = smem_u32(I0) + (uint32_t)(lrow * KP0H) * 2u + (uint32_t)lkq * 16u;
        float cst[4] = {0.f, 0.f, 0.f, 0.f};
        const int xb = tid / 6, xp = tid % 6;

        for (int s = 0; s <= TSTEPS; s++) {
            if (s < TSTEPS) {
                float2 xpv;
                const bool dox = (tid < 96) && (s + 1 < TSTEPS);
                if (dox)
                    xpv = *reinterpret_cast<const float2*>(
                        &x[((size_t)(bbase + xb) * TSTEPS + (s + 1)) * IIN + 2 * xp]);

                float acc[4][4];
#pragma unroll
                for (int u = 0; u < 4; u++) {
                    acc[u][0] = bf[u][0]; acc[u][1] = bf[u][1];
                    acc[u][2] = bf[u][0]; acc[u][3] = bf[u][1];
                }
                uint32_t ab = abase + (uint32_t)(s & 1) * (16 * KP0H * 2);
#pragma unroll
                for (int kt = 0; kt < 4; kt++) {
                    uint32_t a[4];
                    ldmx4(a, ab + kt * 32);
#pragma unroll
                    for (int u = 0; u < 4; u++)
                        mma16(acc[u], a, wb[u][kt][0], wb[u][kt][1]);
                }
                // fused update
                __half* I0n = I0 + ((s + 1) & 1) * 16 * KP0H;
                __half* I1c = I1 + (s & 1) * 16 * KP1H;
#pragma unroll
                for (int u = 0; u < 4; u++) {
                    float t0 = __shfl_xor_sync(0xffffffffu, (m & 1) ? acc[u][0] : acc[u][2], 1);
                    float t1 = __shfl_xor_sync(0xffffffffu, (m & 1) ? acc[u][1] : acc[u][3], 1);
                    float gi, gf, gg, go;
                    if (!(m & 1)) { gi = acc[u][0]; gf = acc[u][1]; gg = t0; go = t1; }
                    else          { gi = t0;        gf = t1;        gg = acc[u][2]; go = acc[u][3]; }
                    int j = 2 * (4 * w + u) + (m >> 1);
                    if (j < HH) {
                        float i_ = fsigmoid(gi), f_ = fsigmoid(gf);
                        float g_ = tanha(gg),   o_ = fsigmoid(go);
                        float cc = f_ * cst[u] + i_ * g_;
                        cst[u] = cc;
                        __half hv = __float2half_rn(o_ * tanha(cc));
                        I0n[bofs * KP0H + IIN + j] = hv;   // layer0 recurrence (t+1)
                        I1c[bofs * KP1H + j]       = hv;   // layer1 input (t)
                    }
                }
                if (dox)
                    *reinterpret_cast<__half2*>(&I0n[xb * KP0H + 2 * xp]) =
                        __halves2half2(__float2half_rn(xpv.x), __float2half_rn(xpv.y));
            }
            __syncthreads();
        }
    } else {
        // ================= LAYER-1 GROUP: warp (w-7) owns ntiles 3i..3i+2 =================
        const int i1 = w - 7;
        uint32_t wb[3][7][2];
        float bf[3][2];
#pragma unroll
        for (int u = 0; u < 3; u++) {
            int t = 3 * i1 + u;
            int nr = t * 8 + (lane >> 2);
            bool ok = nr < 200;
            int org = ok ? orow(nr) : 0;
#pragma unroll
            for (int kt = 0; kt < 7; kt++) {
                int k0 = kt * 16 + 2 * m;
                wb[u][kt][0] = ok ? h2pack(wl1(w_ih1, w_hh1, org, k0),
                                           wl1(w_ih1, w_hh1, org, k0 + 1)) : 0u;
                wb[u][kt][1] = ok ? h2pack(wl1(w_ih1, w_hh1, org, k0 + 8),
                                           wl1(w_ih1, w_hh1, org, k0 + 9)) : 0u;
            }
            int c0 = t * 8 + 2 * m;
            bf[u][0] = (c0 < 200)     ? (b_ih1[orow(c0)]     + b_hh1[orow(c0)])     : 0.f;
            bf[u][1] = (c0 + 1 < 200) ? (b_ih1[orow(c0 + 1)] + b_hh1[orow(c0 + 1)]) : 0.f;
        }
        const uint32_t abase = smem_u32(I1) + (uint32_t)(lrow * KP1H) * 2u + (uint32_t)lkq * 16u;
        float cst[3] = {0.f, 0.f, 0.f};

        for (int s = 0; s <= TSTEPS; s++) {
            if (s >= 1) {
                float acc[3][4];
#pragma unroll
                for (int u = 0; u < 3; u++) {
                    acc[u][0] = bf[u][0]; acc[u][1] = bf[u][1];
                    acc[u][2] = bf[u][0]; acc[u][3] = bf[u][1];
                }
                uint32_t ab = abase + (uint32_t)((s - 1) & 1) * (16 * KP1H * 2);
#pragma unroll
                for (int kt = 0; kt < 7; kt++) {
                    uint32_t a[4];
                    ldmx4(a, ab + kt * 32);
#pragma unroll
                    for (int u = 0; u < 3; u++)
                        mma16(acc[u], a, wb[u][kt][0], wb[u][kt][1]);
                }
                __half* I1c = I1 + (s & 1) * 16 * KP1H;
#pragma unroll
                for (int u = 0; u < 3; u++) {
                    float t0 = __shfl_xor_sync(0xffffffffu, (m & 1) ? acc[u][0] : acc[u][2], 1);
                    float t1 = __shfl_xor_sync(0xffffffffu, (m & 1) ? acc[u][1] : acc[u][3], 1);
                    float gi, gf, gg, go;
                    if (!(m & 1)) { gi = acc[u][0]; gf = acc[u][1]; gg = t0; go = t1; }
                    else          { gi = t0;        gf = t1;        gg = acc[u][2]; go = acc[u][3]; }
                    int j = 2 * (3 * i1 + u) + (m >> 1);
                    if (j < HH) {
                        float i_ = fsigmoid(gi), f_ = fsigmoid(gf);
                        float g_ = tanha(gg),   o_ = fsigmoid(go);
                        float cc = f_ * cst[u] + i_ * g_;
                        cst[u] = cc;
                        I1c[bofs * KP1H + H1OFF + j] = __float2half_rn(o_ * tanha(cc));
                    }
                }
            }
            __syncthreads();
        }
    }

    // head: h1(511) is in I1 buffer (512&1)=0
    if (tid < NB) {
        float acc = b_out[0];
        const __half* hb = I1 + tid * KP1H + H1OFF;
#pragma unroll
        for (int j = 0; j < HH; j++) acc += w_out[j] * __half2float(hb[j]);
        float e = __expf(-acc);
        out[bbase + tid] = __fdividef(1.0f, 1.0f + e);
    }
}

extern "C" void kernel_launch(void* const* d_in, const int* in_sizes, int n_in,
                              void* d_out, int out_size) {
    const float* x     = (const float*)d_in[0];
    const float* w_ih0 = (const float*)d_in[1];
    const float* w_hh0 = (const float*)d_in[2];
    const float* b_ih0 = (const float*)d_in[3];
    const float* b_hh0 = (const float*)d_in[4];
    const float* w_ih1 = (const float*)d_in[5];
    const float* w_hh1 = (const float*)d_in[6];
    const float* b_ih1 = (const float*)d_in[7];
    const float* b_hh1 = (const float*)d_in[8];
    const float* w_out = (const float*)d_in[9];
    const float* b_out = (const float*)d_in[10];
    float* out = (float*)d_out;

    lstm_kernel<<<BTOT / NB, NTH>>>(
        x, w_ih0, w_hh0, b_ih0, b_hh0, w_ih1, w_hh1, b_ih1, b_hh1, w_out, b_out, out);
}